// round 6
// baseline (speedup 1.0000x reference)
#include <cuda_runtime.h>

namespace {
constexpr int kB = 128, kS = 2048, kD = 128, kNQ = 18;
constexpr int TS = 64;                  // s-tile size per CTA
constexpr int HALF_S = kS / 2;          // 1024 s per CTA
constexpr int NTILE = HALF_S / TS;      // 16
constexpr int THREADS = 256;
constexpr float SCALE = 0.08838834764831845f;  // 1/sqrt(128)

constexpr int XBUF_F4 = TS * 32;                 // 2048 float4 per x buffer
constexpr int SMEM_X = 2 * XBUF_F4 * 16;         // 65536 B (double buffer)
constexpr int SMEM_Q = kNQ * kD * 4;             // 9216 B
constexpr int SMEM_P = kNQ * TS * 4;             // 4608 B
constexpr int SMEM_L = 128;
constexpr int SMEM_M = HALF_S * 4;               // 4096 B mask
constexpr int SMEM_BYTES = SMEM_X + SMEM_Q + SMEM_P + SMEM_L + SMEM_M;  // ~83.6KB
constexpr int OUT_PER_B = kNQ * kD;              // 2304
}

// cross-CTA partials (2 CTAs per batch) + arrival counters (zero-init)
__device__ float    g_partP[kB][2][OUT_PER_B];
__device__ float    g_partL[kB][2][kNQ];
__device__ unsigned g_cnt[kB];

// ---- packed f32x2 helpers (B300 FFMA2 path, only reachable via PTX) ----
__device__ __forceinline__ unsigned long long pk2(float a, float b) {
    unsigned long long r;
    asm("mov.b64 %0, {%1,%2};" : "=l"(r) : "f"(a), "f"(b));
    return r;
}
__device__ __forceinline__ unsigned long long f2ma(unsigned long long a,
                                                   unsigned long long b,
                                                   unsigned long long c) {
    unsigned long long d;
    asm("fma.rn.f32x2 %0, %1, %2, %3;" : "=l"(d) : "l"(a), "l"(b), "l"(c));
    return d;
}
__device__ __forceinline__ float2 up2(unsigned long long v) {
    float lo, hi;
    asm("mov.b64 {%0,%1}, %2;" : "=f"(lo), "=f"(hi) : "l"(v));
    return make_float2(lo, hi);
}
__device__ __forceinline__ void cpa16(void* dst, const void* src) {
    unsigned a = (unsigned)__cvta_generic_to_shared(dst);
    asm volatile("cp.async.cg.shared.global [%0], [%1], 16;" :: "r"(a), "l"(src));
}

__global__ void __launch_bounds__(THREADS, 2)
AttentionPooling_main(const float* __restrict__ x,
                      const float* __restrict__ qe,
                      const int*   __restrict__ ques,
                      const int*   __restrict__ mask,
                      float*       __restrict__ out)
{
    extern __shared__ char smem[];
    float4* xb4  = reinterpret_cast<float4*>(smem);
    float*  q_sm = reinterpret_cast<float*>(smem + SMEM_X);
    float*  p_sm = q_sm + kNQ * kD;
    float*  l_sm = p_sm + kNQ * TS;
    int*    m_sm = reinterpret_cast<int*>(smem + SMEM_X + SMEM_Q + SMEM_P + SMEM_L);
    __shared__ int s_flag;

    const int t    = threadIdx.x;
    const int b    = blockIdx.x >> 1;
    const int half = blockIdx.x & 1;

    // ---- mask half -> smem (once, async): 1024 ints = 256 x 16B ----
    {
        const int* mb = mask + b * kS + half * HALF_S;
        cpa16(&m_sm[t * 4], mb + t * 4);
        asm volatile("cp.async.commit_group;");
    }

    // ---- gather q embeddings, pre-scaled; column-swizzled layout:
    // element d4=(dgrp*8+k) stored at col (k*4+dgrp) so phase-A octet reads
    // hit disjoint banks (kills the 4-way LDS conflict).
    for (int i = t; i < kNQ * 32; i += THREADS) {
        int j = i >> 5, d4 = i & 31;
        int qi = ques[b * kNQ + j];
        float4 v = reinterpret_cast<const float4*>(qe + qi * kD)[d4];
        v.x *= SCALE; v.y *= SCALE; v.z *= SCALE; v.w *= SCALE;
        int swz = ((d4 & 7) << 2) | (d4 >> 3);
        reinterpret_cast<float4*>(q_sm)[j * 32 + swz] = v;
    }
    if (t < kNQ) l_sm[t] = 0.0f;

    const float* xb = x + (size_t)b * kS * kD + (size_t)half * HALF_S * kD;

    // swizzled x tile store: col' = (d4 + s) & 31
    auto load_tile = [&](int tile, int buf) {
        const float* src = xb + tile * TS * kD;
        float4* dst = xb4 + buf * XBUF_F4;
        #pragma unroll
        for (int k = 0; k < 8; ++k) {
            int i = t + k * THREADS;              // 2048 float4s
            int s = i >> 5, d4 = i & 31;
            cpa16(&dst[s * 32 + ((d4 + s) & 31)], src + s * kD + d4 * 4);
        }
        asm volatile("cp.async.commit_group;");
    };

    load_tile(0, 0);

    // ---- phase A: 8 warps = qh(2) x sgrp(4 x 16s); lane = dgrp(4) x sslot(8)
    const int w     = t >> 5, lane = t & 31;
    const int qbA   = (w >> 2) * 9;
    const int sgrp  = w & 3;
    const int dgrp  = lane >> 3;
    const int sslot = lane & 7;
    const int srow  = sgrp * 16 + sslot;       // s(si) = srow + si*8, si in {0,1}
    const int sown  = srow + (dgrp & 1) * 8;   // s this lane stores (dgrp<2 only)

    // ---- phase B: 8 warps = qh(2) x slice(4 x 16s); lane = d4
    const int d4B = lane;
    const int qbB = ((t >> 5) & 1) * 9;
    const int slB = t >> 6;                    // 0..3

    unsigned long long acc[9][2];
    #pragma unroll
    for (int j = 0; j < 9; ++j) { acc[j][0] = 0ull; acc[j][1] = 0ull; }

    for (int tile = 0; tile < NTILE; ++tile) {
        const int buf = tile & 1;
        if (tile + 1 < NTILE) {
            load_tile(tile + 1, buf ^ 1);
            asm volatile("cp.async.wait_group 1;");
        } else {
            asm volatile("cp.async.wait_group 0;");
        }
        __syncthreads();

        // ================= phase A =================
        {
            const ulonglong2* xt =
                reinterpret_cast<const ulonglong2*>(xb4 + buf * XBUF_F4);
            const ulonglong2* qt = reinterpret_cast<const ulonglong2*>(q_sm);

            unsigned long long sc[9][2];
            #pragma unroll
            for (int j = 0; j < 9; ++j) { sc[j][0] = 0ull; sc[j][1] = 0ull; }

            #pragma unroll
            for (int k = 0; k < 8; ++k) {
                ulonglong2 xv[2];
                #pragma unroll
                for (int si = 0; si < 2; ++si) {
                    int s = srow + si * 8;
                    int c = (dgrp * 8 + k + s) & 31;
                    xv[si] = xt[s * 32 + c];
                }
                #pragma unroll
                for (int j = 0; j < 9; ++j) {
                    ulonglong2 qv = qt[(qbA + j) * 32 + k * 4 + dgrp];
                    #pragma unroll
                    for (int si = 0; si < 2; ++si) {
                        sc[j][si] = f2ma(xv[si].x, qv.x, sc[j][si]);
                        sc[j][si] = f2ma(xv[si].y, qv.y, sc[j][si]);
                    }
                }
            }

            const int mk = m_sm[tile * TS + sown];
            #pragma unroll
            for (int j = 0; j < 9; ++j) {
                float vs[2];
                #pragma unroll
                for (int si = 0; si < 2; ++si) {
                    float2 f = up2(sc[j][si]);
                    float v = f.x + f.y;
                    v += __shfl_xor_sync(0xffffffffu, v, 8);
                    v += __shfl_xor_sync(0xffffffffu, v, 16);
                    vs[si] = v;
                }
                float vsel = (dgrp & 1) ? vs[1] : vs[0];
                if (dgrp < 2)
                    p_sm[(qbA + j) * TS + sown] = mk ? __expf(vsel) : 0.0f;
            }
        }
        __syncthreads();

        // ---- row-sums of p into l (72 threads) ----
        if (t < kNQ * 4) {
            int q = t >> 2, w4 = t & 3;
            const float4* pr = reinterpret_cast<const float4*>(p_sm + q * TS + w4 * 16);
            float ss = 0.0f;
            #pragma unroll
            for (int k2 = 0; k2 < 4; ++k2) {
                float4 v = pr[k2];
                ss += (v.x + v.y) + (v.z + v.w);
            }
            atomicAdd(&l_sm[q], ss);
        }

        // ================= phase B =================
        {
            const ulonglong2* xt =
                reinterpret_cast<const ulonglong2*>(xb4 + buf * XBUF_F4);
            #pragma unroll
            for (int i = 0; i < 4; ++i) {
                const int s0 = slB * 16 + i * 4;
                ulonglong2 xq[4];
                #pragma unroll
                for (int k2 = 0; k2 < 4; ++k2)
                    xq[k2] = xt[(s0 + k2) * 32 + ((d4B + s0 + k2) & 31)];
                #pragma unroll
                for (int j = 0; j < 9; ++j) {
                    float4 pv = reinterpret_cast<const float4*>(
                        p_sm + (qbB + j) * TS)[slB * 4 + i];
                    unsigned long long p0 = pk2(pv.x, pv.x);
                    acc[j][0] = f2ma(xq[0].x, p0, acc[j][0]);
                    acc[j][1] = f2ma(xq[0].y, p0, acc[j][1]);
                    unsigned long long p1 = pk2(pv.y, pv.y);
                    acc[j][0] = f2ma(xq[1].x, p1, acc[j][0]);
                    acc[j][1] = f2ma(xq[1].y, p1, acc[j][1]);
                    unsigned long long p2 = pk2(pv.z, pv.z);
                    acc[j][0] = f2ma(xq[2].x, p2, acc[j][0]);
                    acc[j][1] = f2ma(xq[2].y, p2, acc[j][1]);
                    unsigned long long p3 = pk2(pv.w, pv.w);
                    acc[j][0] = f2ma(xq[3].x, p3, acc[j][0]);
                    acc[j][1] = f2ma(xq[3].y, p3, acc[j][1]);
                }
            }
        }
        __syncthreads();
    }

    // ---- reduce 4 slices x 2 q-halves through smem (reuse x area) ----
    float* red = reinterpret_cast<float*>(smem);   // 4*18*128*4 = 36864 B
    #pragma unroll
    for (int j = 0; j < 9; ++j) {
        float2 a = up2(acc[j][0]);
        float2 c = up2(acc[j][1]);
        reinterpret_cast<float4*>(red)[(slB * kNQ + (qbB + j)) * 32 + d4B] =
            make_float4(a.x, a.y, c.x, c.y);
    }
    __syncthreads();

    // ---- write per-CTA partials to global ----
    float* P = g_partP[b][half];
    for (int o = t; o < OUT_PER_B; o += THREADS) {
        float s0 = red[0 * OUT_PER_B + o] + red[1 * OUT_PER_B + o];
        float s1 = red[2 * OUT_PER_B + o] + red[3 * OUT_PER_B + o];
        P[o] = s0 + s1;
    }
    if (t < kNQ) g_partL[b][half][t] = l_sm[t];
    __syncthreads();

    // ---- last-arriver combines (deterministic order, counter self-resets) ----
    if (t == 0) {
        __threadfence();
        s_flag = (int)atomicAdd(&g_cnt[b], 1u);
    }
    __syncthreads();
    if (s_flag == 1) {
        __threadfence();   // acquire partner CTA's writes
        if (t < kNQ)
            l_sm[t] = 1.0f / (g_partL[b][0][t] + g_partL[b][1][t]);
        __syncthreads();
        const float* P0 = g_partP[b][0];
        const float* P1 = g_partP[b][1];
        float* ob = out + (size_t)b * OUT_PER_B;
        for (int o = t; o < OUT_PER_B; o += THREADS)
            ob[o] = (P0[o] + P1[o]) * l_sm[o >> 7];
        if (t == 0) g_cnt[b] = 0;   // reset for next graph replay
    }
}

extern "C" void kernel_launch(void* const* d_in, const int* in_sizes, int n_in,
                              void* d_out, int out_size) {
    const float* x    = (const float*)d_in[0];
    const float* qe   = (const float*)d_in[1];
    const int*   ques = (const int*)d_in[2];
    const int*   mask = (const int*)d_in[3];
    float* out = (float*)d_out;

    cudaFuncSetAttribute(AttentionPooling_main,
                         cudaFuncAttributeMaxDynamicSharedMemorySize, SMEM_BYTES);
    AttentionPooling_main<<<2 * kB, THREADS, SMEM_BYTES>>>(x, qe, ques, mask, out);
}